// round 6
// baseline (speedup 1.0000x reference)
#include <cuda_runtime.h>
#include <cuda_fp16.h>
#include <cstdint>

// CapsuleLayer dynamic routing, 3 rounds.
// x: [512, 1152, 8] fp32   W: [10, 1152, 8, 16] fp32   out: [10, 512, 16] fp32
//
// Pre-pass: repack W (fp32, bitwise identical) into caps_Wq: full-line
// coalesced LDG.128 with all 8 i's lane-local (no cross-lane merge).
// Phase 1: priors GEMM (f32x2 FMA), priors -> fp16 smem; S0 = sum_r p_r
// fused into the GEMM (fp32 accumulation, 16 shfl + 8 STS per lane).
// Phase 2: each thread loads its 6 rows ONCE into registers; both rounds'
// a-pass and S-pass run from registers. Reductions: 16-shfl split-exchange
// tree + per-group named barriers. w = v0, then v0+v1 (logits additive in p).

#define NCAPS 10
#define NB    512
#define NR    1152
#define CI    8
#define CO    16
#define BT    4
#define NTHREADS 768
#define GROUPS (NB / BT)          // 128
#define TPB   192                 // threads per batch group (6 warps)
#define WPG   6
#define KPT   (NR / TPB)          // 6 rows per thread in routing
#define NWARP (NTHREADS / 32)     // 24
#define QITER (NR / (NWARP * 4))  // 12 row-quads per warp in phase 1
#define PSTR  20                  // halves per prior row (16 data + 4 pad)

// shared memory layout (bytes)
#define P_BYTES    (BT * NR * PSTR * 2)   // 184320 fp16 priors
#define SRED_OFF   P_BYTES
#define SRED_BYTES (BT * WPG * CO * 4)    // 1536
#define WRED_OFF   (SRED_OFF + SRED_BYTES)
#define WRED_BYTES (BT * 2 * WPG * 4)     // 192
#define VDOT_OFF   (WRED_OFF + WRED_BYTES)
#define VDOT_BYTES (BT * CO * 4)          // 256
#define S0_OFF     (VDOT_OFF + VDOT_BYTES)
#define S0_BYTES   (NWARP * BT * 8 * 8)   // 6144  per-warp fp32 S0 partials
#define SMEM_TOTAL (S0_OFF + S0_BYTES)

// repacked W, fp32, [NCAPS*NR] rows x 128 floats
__device__ __align__(16) float caps_Wq[NCAPS * NR * CI * CO];

__device__ __forceinline__ void fma2(unsigned long long& d,
                                     unsigned long long a,
                                     unsigned long long b) {
    asm("fma.rn.f32x2 %0, %1, %2, %0;" : "+l"(d) : "l"(a), "l"(b));
}
__device__ __forceinline__ void add2(unsigned long long& d,
                                     unsigned long long a) {
    asm("add.rn.f32x2 %0, %0, %1;" : "+l"(d) : "l"(a));
}
__device__ __forceinline__ unsigned long long pack2(float x) {
    unsigned long long r;
    asm("mov.b64 %0, {%1, %1};" : "=l"(r) : "f"(x));
    return r;
}
__device__ __forceinline__ unsigned long long packf2(float x, float y) {
    unsigned long long r;
    asm("mov.b64 %0, {%1, %2};" : "=l"(r) : "f"(x), "f"(y));
    return r;
}
__device__ __forceinline__ float2 unpack2(unsigned long long v) {
    float2 f;
    asm("mov.b64 {%0, %1}, %2;" : "=f"(f.x), "=f"(f.y) : "l"(v));
    return f;
}
__device__ __forceinline__ void bar_group(int id) {
    asm volatile("bar.sync %0, %1;" :: "r"(id), "r"(TPB) : "memory");
}
__device__ __forceinline__ float2 h2f(uint32_t h) {
    return __half22float2(*(const __half2*)&h);
}

// Split-exchange reduce of S[16] over 32 lanes: 16 shfl total.
__device__ __forceinline__ void reduce_s16(float S[CO], int lane,
                                           float* sred_warp) {
    const bool h16 = lane & 16;
    #pragma unroll
    for (int j = 0; j < 8; ++j) {
        const float snd = h16 ? S[j] : S[j + 8];
        const float kp  = h16 ? S[j + 8] : S[j];
        S[j] = kp + __shfl_xor_sync(0xffffffffu, snd, 16);
    }
    const bool h8 = lane & 8;
    #pragma unroll
    for (int j = 0; j < 4; ++j) {
        const float snd = h8 ? S[j] : S[j + 4];
        const float kp  = h8 ? S[j + 4] : S[j];
        S[j] = kp + __shfl_xor_sync(0xffffffffu, snd, 8);
    }
    const bool h4 = lane & 4;
    #pragma unroll
    for (int j = 0; j < 2; ++j) {
        const float snd = h4 ? S[j] : S[j + 2];
        const float kp  = h4 ? S[j + 2] : S[j];
        S[j] = kp + __shfl_xor_sync(0xffffffffu, snd, 4);
    }
    const bool h2 = lane & 2;
    {
        const float snd = h2 ? S[0] : S[1];
        const float kp  = h2 ? S[1] : S[0];
        S[0] = kp + __shfl_xor_sync(0xffffffffu, snd, 2);
    }
    S[0] += __shfl_xor_sync(0xffffffffu, S[0], 1);
    const int comp = ((lane >> 4) & 1) * 8 + ((lane >> 3) & 1) * 4 +
                     ((lane >> 2) & 1) * 2 + ((lane >> 1) & 1);
    if (!(lane & 1)) sred_warp[comp] = S[0];
}

// ---------- W repack kernel: 1 thread = one 16B output chunk ----------
__global__ void __launch_bounds__(256)
repack_kernel(const float* __restrict__ W) {
    const int idx = blockIdx.x * blockDim.x + threadIdx.x;
    if (idx >= NCAPS * NR * 32) return;
    const int row = idx >> 5;         // (n*NR + r)
    const int t5  = idx & 31;
    const int c   = t5 >> 3;          // 0..3
    const int op  = t5 & 7;           // 0..7
    const float* src = W + (size_t)row * 128;
    const float2 lo = *(const float2*)(src + (2*c)     * 16 + 2*op);
    const float2 hi = *(const float2*)(src + (2*c + 1) * 16 + 2*op);
    float4 o;
    o.x = lo.x; o.y = lo.y; o.z = hi.x; o.w = hi.y;
    *(float4*)(caps_Wq + (size_t)row * 128 + c * 32 + op * 4) = o;
}

__global__ void __launch_bounds__(NTHREADS, 1)
caps_kernel(const float* __restrict__ x,
            float* __restrict__ out) {
    extern __shared__ char smem[];
    __half* p    = (__half*)smem;
    float* sred  = (float*)(smem + SRED_OFF);
    float* wred  = (float*)(smem + WRED_OFF);
    float* vdot  = (float*)(smem + VDOT_OFF);
    float* s0red = (float*)(smem + S0_OFF);   // [warp][b][op] float2

    const int n  = blockIdx.y;
    const int b0 = blockIdx.x * BT;
    const int t  = threadIdx.x;
    const int wid  = t >> 5;
    const int lane = t & 31;

    // ======== Phase 1: priors GEMM + fused S0 accumulation ========
    // lane = (rl 0..3, op 0..7)
    {
        const int rl = lane >> 3;
        const int op = lane & 7;
        unsigned long long s0[BT];
        #pragma unroll
        for (int b = 0; b < BT; ++b) s0[b] = 0ull;

        #pragma unroll 2
        for (int j = 0; j < QITER; ++j) {
            const int r = (wid + j * NWARP) * 4 + rl;
            const float4* wq =
                (const float4*)caps_Wq + ((size_t)n * NR + r) * 32 + op;
            float4 wc[4];
            #pragma unroll
            for (int c = 0; c < 4; ++c) wc[c] = wq[c * 8];
            float xv[BT][CI];
            #pragma unroll
            for (int b = 0; b < BT; ++b) {
                const float4* xp =
                    (const float4*)(x + ((size_t)(b0 + b) * NR + r) * CI);
                const float4 x0 = xp[0], x1 = xp[1];
                xv[b][0]=x0.x; xv[b][1]=x0.y; xv[b][2]=x0.z; xv[b][3]=x0.w;
                xv[b][4]=x1.x; xv[b][5]=x1.y; xv[b][6]=x1.z; xv[b][7]=x1.w;
            }
            unsigned long long acc[BT];
            #pragma unroll
            for (int b = 0; b < BT; ++b) acc[b] = 0ull;
            #pragma unroll
            for (int c = 0; c < 4; ++c) {
                const unsigned long long wlo = packf2(wc[c].x, wc[c].y);
                const unsigned long long whi = packf2(wc[c].z, wc[c].w);
                #pragma unroll
                for (int b = 0; b < BT; ++b) {
                    fma2(acc[b], pack2(xv[b][2*c    ]), wlo);
                    fma2(acc[b], pack2(xv[b][2*c + 1]), whi);
                }
            }
            #pragma unroll
            for (int b = 0; b < BT; ++b) {
                add2(s0[b], acc[b]);                       // fused S0
                const float2 f = unpack2(acc[b]);
                *(__half2*)(p + (size_t)(b * NR + r) * PSTR + op * 2) =
                    __floats2half2_rn(f.x, f.y);
            }
        }
        // reduce s0 over rl (lane bits 3,4); lanes<8 store per-warp partial
        #pragma unroll
        for (int b = 0; b < BT; ++b) {
            float2 f = unpack2(s0[b]);
            f.x += __shfl_xor_sync(0xffffffffu, f.x, 8);
            f.y += __shfl_xor_sync(0xffffffffu, f.y, 8);
            f.x += __shfl_xor_sync(0xffffffffu, f.x, 16);
            f.y += __shfl_xor_sync(0xffffffffu, f.y, 16);
            if (rl == 0)
                *(float2*)(s0red + ((wid * BT + b) * 8 + op) * 2) = f;
        }
    }
    __syncthreads();

    // ======== Phase 2: routing, rows register-resident ========
    const int b    = t / TPB;      // 0..3
    const int tb   = t % TPB;      // 0..191
    const int wl   = tb >> 5;      // warp in group 0..5
    const int bid  = b + 1;        // named barrier id
    const __half* pb = p + (size_t)b * NR * PSTR;
    float* sredb = sred + b * WPG * CO;
    float* wredb = wred + b * 2 * WPG;
    float* vdotb = vdot + b * CO;

    // one LDS pass: 6 rows -> 48 registers, used by both rounds
    uint2 rows[KPT][4];
    #pragma unroll
    for (int k = 0; k < KPT; ++k) {
        const uint2* src = (const uint2*)(pb + (size_t)(tb + k * TPB) * PSTR);
        #pragma unroll
        for (int q = 0; q < 4; ++q) rows[k][q] = src[q];
    }

    // ---- v0 = squash(mean_r p_r) from fused S0 partials ----
    if (tb < CO) {
        float s = 0.f;
        #pragma unroll
        for (int w = 0; w < NWARP; ++w)
            s += s0red[((w * BT + b) * 8 + (tb >> 1)) * 2 + (tb & 1)];
        const float v = s * (1.0f / NR);
        float sq = v * v;
        #pragma unroll
        for (int off = 8; off; off >>= 1)
            sq += __shfl_xor_sync(0xffffu, sq, off);
        const float coef = sq / ((1.f + sq) * sqrtf(sq));
        vdotb[tb] = v * coef;
    }
    bar_group(bid);

    // ---- rounds 1 and 2 (rows stay in registers) ----
    #pragma unroll
    for (int round = 0; round < 2; ++round) {
        float a[KPT];
        float mloc = -1e30f;
        {
            float vd[CO];
            #pragma unroll
            for (int o = 0; o < CO; ++o) vd[o] = vdotb[o];
            #pragma unroll
            for (int k = 0; k < KPT; ++k) {
                float s = 0.f;
                #pragma unroll
                for (int q = 0; q < 4; ++q) {
                    const float2 f0 = h2f(rows[k][q].x);
                    const float2 f1 = h2f(rows[k][q].y);
                    s += f0.x * vd[4*q+0] + f0.y * vd[4*q+1]
                       + f1.x * vd[4*q+2] + f1.y * vd[4*q+3];
                }
                a[k] = s;
                mloc = fmaxf(mloc, s);
            }
        }
        #pragma unroll
        for (int off = 16; off; off >>= 1)
            mloc = fmaxf(mloc, __shfl_xor_sync(0xffffffffu, mloc, off));
        if (lane == 0) wredb[wl] = mloc;
        bar_group(bid);
        float m = wredb[0];
        #pragma unroll
        for (int w = 1; w < WPG; ++w) m = fmaxf(m, wredb[w]);

        float zloc = 0.f;
        #pragma unroll
        for (int k = 0; k < KPT; ++k) {
            a[k] = __expf(a[k] - m);
            zloc += a[k];
        }
        #pragma unroll
        for (int off = 16; off; off >>= 1)
            zloc += __shfl_xor_sync(0xffffffffu, zloc, off);
        if (lane == 0) wredb[WPG + wl] = zloc;
        bar_group(bid);
        float Z = wredb[WPG];
        #pragma unroll
        for (int w = 1; w < WPG; ++w) Z += wredb[WPG + w];

        float S[CO];
        #pragma unroll
        for (int o = 0; o < CO; ++o) S[o] = 0.f;
        #pragma unroll
        for (int k = 0; k < KPT; ++k) {
            const float e = a[k];
            #pragma unroll
            for (int q = 0; q < 4; ++q) {
                const float2 f0 = h2f(rows[k][q].x);
                const float2 f1 = h2f(rows[k][q].y);
                S[4*q+0] += e * f0.x; S[4*q+1] += e * f0.y;
                S[4*q+2] += e * f1.x; S[4*q+3] += e * f1.y;
            }
        }
        reduce_s16(S, lane, sredb + wl * CO);
        bar_group(bid);

        if (tb < CO) {
            float s = 0.f;
            #pragma unroll
            for (int w = 0; w < WPG; ++w) s += sredb[w * CO + tb];
            const float v = s / Z;
            float sq = v * v;
            #pragma unroll
            for (int off = 8; off; off >>= 1)
                sq += __shfl_xor_sync(0xffffu, sq, off);
            const float coef = sq / ((1.f + sq) * sqrtf(sq));
            const float res = v * coef;
            if (round == 0)
                vdotb[tb] += res;                       // w = v0 + v1
            else
                out[((size_t)n * NB + (b0 + b)) * CO + tb] = res;
        }
        bar_group(bid);
    }
}

extern "C" void kernel_launch(void* const* d_in, const int* in_sizes, int n_in,
                              void* d_out, int out_size) {
    (void)in_sizes; (void)n_in; (void)out_size;
    const float* x = (const float*)d_in[0];
    const float* W = (const float*)d_in[1];
    float* out = (float*)d_out;

    // repack W -> caps_Wq (stream-ordered before main kernel)
    const int total = NCAPS * NR * 32;
    repack_kernel<<<(total + 255) / 256, 256>>>(W);

    cudaFuncSetAttribute(caps_kernel,
                         cudaFuncAttributeMaxDynamicSharedMemorySize, SMEM_TOTAL);
    dim3 grid(GROUPS, NCAPS);
    caps_kernel<<<grid, NTHREADS, SMEM_TOTAL>>>(x, out);
}

// round 7
// speedup vs baseline: 1.3777x; 1.3777x over previous
#include <cuda_runtime.h>
#include <cuda_fp16.h>
#include <cstdint>

// CapsuleLayer dynamic routing, 3 rounds.
// x: [512, 1152, 8] fp32   W: [10, 1152, 8, 16] fp32   out: [10, 512, 16] fp32
//
// Pre-pass: repack W (fp32, bitwise identical) into caps_Wq: full-line
// coalesced LDG.128 with all 8 i's lane-local.
// Phase 1: priors GEMM (f32x2 FMA) -> fp16 smem; S0 = sum_r p_r fused into
// the GEMM in fp32 (8 extra regs, 16 shfl + 8 STS per lane).
// Phase 2 (routing): rows are STREAMED from smem (never held in registers --
// the R4/R6 spill trap). Softmax is computed max-free (shift-invariant;
// |a|<~20 so exp cannot overflow), which fuses a/e/Z/S into ONE pass per
// round: 2 row passes total instead of 5. w = v0, then v0+v1.

#define NCAPS 10
#define NB    512
#define NR    1152
#define CI    8
#define CO    16
#define BT    4
#define NTHREADS 768
#define GROUPS (NB / BT)          // 128
#define TPB   192                 // threads per batch group (6 warps)
#define WPG   6
#define KPT   (NR / TPB)          // 6 rows per thread in routing
#define NWARP (NTHREADS / 32)     // 24
#define QITER (NR / (NWARP * 4))  // 12 row-quads per warp in phase 1
#define PSTR  20                  // halves per prior row (16 data + 4 pad)

// shared memory layout (bytes)
#define P_BYTES    (BT * NR * PSTR * 2)   // 184320 fp16 priors
#define SRED_OFF   P_BYTES
#define SRED_BYTES (BT * WPG * CO * 4)    // 1536
#define WRED_OFF   (SRED_OFF + SRED_BYTES)
#define WRED_BYTES (BT * WPG * 4)         // 96   per-warp Z partials
#define VDOT_OFF   (WRED_OFF + WRED_BYTES)
#define VDOT_BYTES (BT * CO * 4)          // 256
#define S0_OFF     (VDOT_OFF + VDOT_BYTES)
#define S0_BYTES   (NWARP * BT * 8 * 8)   // 6144 per-warp fp32 S0 partials
#define SMEM_TOTAL (S0_OFF + S0_BYTES)

// repacked W, fp32, [NCAPS*NR] rows x 128 floats
__device__ __align__(16) float caps_Wq[NCAPS * NR * CI * CO];

struct __align__(8) H4 { __half2 a, b; };

__device__ __forceinline__ void fma2(unsigned long long& d,
                                     unsigned long long a,
                                     unsigned long long b) {
    asm("fma.rn.f32x2 %0, %1, %2, %0;" : "+l"(d) : "l"(a), "l"(b));
}
__device__ __forceinline__ void add2(unsigned long long& d,
                                     unsigned long long a) {
    asm("add.rn.f32x2 %0, %0, %1;" : "+l"(d) : "l"(a));
}
__device__ __forceinline__ unsigned long long pack2(float x) {
    unsigned long long r;
    asm("mov.b64 %0, {%1, %1};" : "=l"(r) : "f"(x));
    return r;
}
__device__ __forceinline__ unsigned long long packf2(float x, float y) {
    unsigned long long r;
    asm("mov.b64 %0, {%1, %2};" : "=l"(r) : "f"(x), "f"(y));
    return r;
}
__device__ __forceinline__ float2 unpack2(unsigned long long v) {
    float2 f;
    asm("mov.b64 {%0, %1}, %2;" : "=f"(f.x), "=f"(f.y) : "l"(v));
    return f;
}
__device__ __forceinline__ void bar_group(int id) {
    asm volatile("bar.sync %0, %1;" :: "r"(id), "r"(TPB) : "memory");
}
__device__ __forceinline__ void load_rowf(const __half* pr, float f[CO]) {
    #pragma unroll
    for (int q = 0; q < 4; ++q) {
        const H4 u = *(const H4*)(pr + q * 4);
        const float2 f0 = __half22float2(u.a);
        const float2 f1 = __half22float2(u.b);
        f[q*4+0] = f0.x; f[q*4+1] = f0.y; f[q*4+2] = f1.x; f[q*4+3] = f1.y;
    }
}

// Split-exchange reduce of S[16] over 32 lanes: 16 shfl total.
__device__ __forceinline__ void reduce_s16(float S[CO], int lane,
                                           float* sred_warp) {
    const bool h16 = lane & 16;
    #pragma unroll
    for (int j = 0; j < 8; ++j) {
        const float snd = h16 ? S[j] : S[j + 8];
        const float kp  = h16 ? S[j + 8] : S[j];
        S[j] = kp + __shfl_xor_sync(0xffffffffu, snd, 16);
    }
    const bool h8 = lane & 8;
    #pragma unroll
    for (int j = 0; j < 4; ++j) {
        const float snd = h8 ? S[j] : S[j + 4];
        const float kp  = h8 ? S[j + 4] : S[j];
        S[j] = kp + __shfl_xor_sync(0xffffffffu, snd, 8);
    }
    const bool h4 = lane & 4;
    #pragma unroll
    for (int j = 0; j < 2; ++j) {
        const float snd = h4 ? S[j] : S[j + 2];
        const float kp  = h4 ? S[j + 2] : S[j];
        S[j] = kp + __shfl_xor_sync(0xffffffffu, snd, 4);
    }
    const bool h2 = lane & 2;
    {
        const float snd = h2 ? S[0] : S[1];
        const float kp  = h2 ? S[1] : S[0];
        S[0] = kp + __shfl_xor_sync(0xffffffffu, snd, 2);
    }
    S[0] += __shfl_xor_sync(0xffffffffu, S[0], 1);
    const int comp = ((lane >> 4) & 1) * 8 + ((lane >> 3) & 1) * 4 +
                     ((lane >> 2) & 1) * 2 + ((lane >> 1) & 1);
    if (!(lane & 1)) sred_warp[comp] = S[0];
}

// ---------- W repack kernel ----------
__global__ void __launch_bounds__(256)
repack_kernel(const float* __restrict__ W) {
    const int idx = blockIdx.x * blockDim.x + threadIdx.x;
    if (idx >= NCAPS * NR * 32) return;
    const int row = idx >> 5;
    const int t5  = idx & 31;
    const int c   = t5 >> 3;
    const int op  = t5 & 7;
    const float* src = W + (size_t)row * 128;
    const float2 lo = *(const float2*)(src + (2*c)     * 16 + 2*op);
    const float2 hi = *(const float2*)(src + (2*c + 1) * 16 + 2*op);
    float4 o;
    o.x = lo.x; o.y = lo.y; o.z = hi.x; o.w = hi.y;
    *(float4*)(caps_Wq + (size_t)row * 128 + c * 32 + op * 4) = o;
}

__global__ void __launch_bounds__(NTHREADS, 1)
caps_kernel(const float* __restrict__ x,
            float* __restrict__ out) {
    extern __shared__ char smem[];
    __half* p    = (__half*)smem;
    float* sred  = (float*)(smem + SRED_OFF);
    float* wred  = (float*)(smem + WRED_OFF);
    float* vdot  = (float*)(smem + VDOT_OFF);
    float* s0red = (float*)(smem + S0_OFF);

    const int n  = blockIdx.y;
    const int b0 = blockIdx.x * BT;
    const int t  = threadIdx.x;
    const int wid  = t >> 5;
    const int lane = t & 31;

    // ======== Phase 1: priors GEMM + fused fp32 S0 ========
    // lane = (rl 0..3, op 0..7)
    {
        const int rl = lane >> 3;
        const int op = lane & 7;
        unsigned long long s0[BT];
        #pragma unroll
        for (int b = 0; b < BT; ++b) s0[b] = 0ull;

        #pragma unroll 2
        for (int j = 0; j < QITER; ++j) {
            const int r = (wid + j * NWARP) * 4 + rl;
            const float4* wq =
                (const float4*)caps_Wq + ((size_t)n * NR + r) * 32 + op;
            float4 wc[4];
            #pragma unroll
            for (int c = 0; c < 4; ++c) wc[c] = wq[c * 8];
            float xv[BT][CI];
            #pragma unroll
            for (int b = 0; b < BT; ++b) {
                const float4* xp =
                    (const float4*)(x + ((size_t)(b0 + b) * NR + r) * CI);
                const float4 x0 = xp[0], x1 = xp[1];
                xv[b][0]=x0.x; xv[b][1]=x0.y; xv[b][2]=x0.z; xv[b][3]=x0.w;
                xv[b][4]=x1.x; xv[b][5]=x1.y; xv[b][6]=x1.z; xv[b][7]=x1.w;
            }
            unsigned long long acc[BT];
            #pragma unroll
            for (int b = 0; b < BT; ++b) acc[b] = 0ull;
            #pragma unroll
            for (int c = 0; c < 4; ++c) {
                const unsigned long long wlo = packf2(wc[c].x, wc[c].y);
                const unsigned long long whi = packf2(wc[c].z, wc[c].w);
                #pragma unroll
                for (int b = 0; b < BT; ++b) {
                    fma2(acc[b], pack2(xv[b][2*c    ]), wlo);
                    fma2(acc[b], pack2(xv[b][2*c + 1]), whi);
                }
            }
            #pragma unroll
            for (int b = 0; b < BT; ++b) {
                add2(s0[b], acc[b]);
                const float2 f = unpack2(acc[b]);
                *(__half2*)(p + (size_t)(b * NR + r) * PSTR + op * 2) =
                    __floats2half2_rn(f.x, f.y);
            }
        }
        #pragma unroll
        for (int b = 0; b < BT; ++b) {
            float2 f = unpack2(s0[b]);
            f.x += __shfl_xor_sync(0xffffffffu, f.x, 8);
            f.y += __shfl_xor_sync(0xffffffffu, f.y, 8);
            f.x += __shfl_xor_sync(0xffffffffu, f.x, 16);
            f.y += __shfl_xor_sync(0xffffffffu, f.y, 16);
            if (rl == 0)
                *(float2*)(s0red + ((wid * BT + b) * 8 + op) * 2) = f;
        }
    }
    __syncthreads();

    // ======== Phase 2: routing, streamed rows, max-free softmax ========
    const int b    = t / TPB;      // 0..3
    const int tb   = t % TPB;      // 0..191
    const int wl   = tb >> 5;      // warp in group 0..5
    const int bid  = b + 1;
    const __half* pb = p + (size_t)b * NR * PSTR;
    float* sredb = sred + b * WPG * CO;
    float* wredb = wred + b * WPG;
    float* vdotb = vdot + b * CO;

    // ---- v0 = squash(mean_r p_r) from fused S0 partials ----
    if (tb < CO) {
        float s = 0.f;
        #pragma unroll
        for (int w = 0; w < NWARP; ++w)
            s += s0red[((w * BT + b) * 8 + (tb >> 1)) * 2 + (tb & 1)];
        const float v = s * (1.0f / NR);
        float sq = v * v;
        #pragma unroll
        for (int off = 8; off; off >>= 1)
            sq += __shfl_xor_sync(0xffffu, sq, off);
        const float coef = sq / ((1.f + sq) * sqrtf(sq));
        vdotb[tb] = v * coef;
    }
    bar_group(bid);

    // ---- rounds 1 and 2: single streamed pass per round ----
    #pragma unroll
    for (int round = 0; round < 2; ++round) {
        float vd[CO];
        #pragma unroll
        for (int o = 0; o < CO; ++o) vd[o] = vdotb[o];

        float S[CO];
        #pragma unroll
        for (int o = 0; o < CO; ++o) S[o] = 0.f;
        float zloc = 0.f;

        #pragma unroll
        for (int k = 0; k < KPT; ++k) {
            float f[CO];
            load_rowf(pb + (size_t)(tb + k * TPB) * PSTR, f);
            float a = 0.f;
            #pragma unroll
            for (int o = 0; o < CO; ++o) a += f[o] * vd[o];
            const float e = __expf(a);      // max-free: |a| <~ 20, safe
            zloc += e;
            #pragma unroll
            for (int o = 0; o < CO; ++o) S[o] += e * f[o];
        }
        #pragma unroll
        for (int off = 16; off; off >>= 1)
            zloc += __shfl_xor_sync(0xffffffffu, zloc, off);
        if (lane == 0) wredb[wl] = zloc;
        reduce_s16(S, lane, sredb + wl * CO);
        bar_group(bid);

        if (tb < CO) {
            float s = 0.f;
            #pragma unroll
            for (int w = 0; w < WPG; ++w) s += sredb[w * CO + tb];
            float Z = wredb[0];
            #pragma unroll
            for (int w = 1; w < WPG; ++w) Z += wredb[w];
            const float v = s / Z;
            float sq = v * v;
            #pragma unroll
            for (int off = 8; off; off >>= 1)
                sq += __shfl_xor_sync(0xffffu, sq, off);
            const float coef = sq / ((1.f + sq) * sqrtf(sq));
            const float res = v * coef;
            if (round == 0)
                vdotb[tb] += res;                       // w = v0 + v1
            else
                out[((size_t)n * NB + (b0 + b)) * CO + tb] = res;
        }
        bar_group(bid);
    }
}

extern "C" void kernel_launch(void* const* d_in, const int* in_sizes, int n_in,
                              void* d_out, int out_size) {
    (void)in_sizes; (void)n_in; (void)out_size;
    const float* x = (const float*)d_in[0];
    const float* W = (const float*)d_in[1];
    float* out = (float*)d_out;

    const int total = NCAPS * NR * 32;
    repack_kernel<<<(total + 255) / 256, 256>>>(W);

    cudaFuncSetAttribute(caps_kernel,
                         cudaFuncAttributeMaxDynamicSharedMemorySize, SMEM_TOTAL);
    dim3 grid(GROUPS, NCAPS);
    caps_kernel<<<grid, NTHREADS, SMEM_TOTAL>>>(x, out);
}

// round 8
// speedup vs baseline: 1.5884x; 1.1529x over previous
#include <cuda_runtime.h>
#include <cuda_fp16.h>
#include <cstdint>

// CapsuleLayer dynamic routing, 3 rounds.
// x: [512, 1152, 8] fp32   W: [10, 1152, 8, 16] fp32   out: [10, 512, 16] fp32
//
// Pre-pass: repack W into caps_Wq2 (fp32, bitwise identical):
//   Wq2[n][g][i][rq][oq] (float4) = W[n][g*8+rq][i][4*oq..4*oq+3]
//   -> phase-1 warp instr i reads 32 consecutive float4 = 512B contiguous
//      (4 wf per LDG.128, the L1 minimum for W's 576KB/block).
// Phase 1: warp = row-octet; lane = (rq 0..7, oq 0..3). Lane computes its
//   row's o-quad for 4 batches (b-pair split keeps ~70 live regs, no spills).
//   Priors -> fp16 smem, PSTR=16 halves + XOR chunk swizzle
//   (chunk q at q ^ ((r>>2)&3)): conflict-free STS.64 and LDS.64.
// Phase 2: streamed rows (never register-resident), max-free softmax
//   (shift-invariant, |a|<~20): one fused a/e/Z/S pass per round.
//   v0 = squash(mean p) from its own streamed pass. w = v0, then v0+v1.

#define NCAPS 10
#define NB    512
#define NR    1152
#define CI    8
#define CO    16
#define BT    4
#define NTHREADS 768
#define GROUPS (NB / BT)          // 128
#define TPB   192                 // threads per batch group (6 warps)
#define WPG   6
#define KPT   (NR / TPB)          // 6 rows per thread in routing
#define NWARP (NTHREADS / 32)     // 24
#define OCT   (NR / 8)            // 144 row-octets
#define JIT   (OCT / NWARP)       // 6 octets per warp
#define PSTR  16                  // halves per prior row (exact, swizzled)

// shared memory layout (bytes)
#define P_BYTES    (BT * NR * PSTR * 2)   // 147456 fp16 priors
#define SRED_OFF   P_BYTES
#define SRED_BYTES (BT * WPG * CO * 4)    // 1536
#define WRED_OFF   (SRED_OFF + SRED_BYTES)
#define WRED_BYTES (BT * WPG * 4)         // 96
#define VDOT_OFF   (WRED_OFF + WRED_BYTES)
#define VDOT_BYTES (BT * CO * 4)          // 256
#define SMEM_TOTAL (VDOT_OFF + VDOT_BYTES)

// repacked W: [NCAPS][OCT][CI][8 rq][4 oq] float4
__device__ __align__(16) float caps_Wq2[NCAPS * NR * CI * CO];

struct __align__(8) H4 { __half2 a, b; };

__device__ __forceinline__ void fma2(unsigned long long& d,
                                     unsigned long long a,
                                     unsigned long long b) {
    asm("fma.rn.f32x2 %0, %1, %2, %0;" : "+l"(d) : "l"(a), "l"(b));
}
__device__ __forceinline__ unsigned long long pack2(float x) {
    unsigned long long r;
    asm("mov.b64 %0, {%1, %1};" : "=l"(r) : "f"(x));
    return r;
}
__device__ __forceinline__ unsigned long long packf2(float x, float y) {
    unsigned long long r;
    asm("mov.b64 %0, {%1, %2};" : "=l"(r) : "f"(x), "f"(y));
    return r;
}
__device__ __forceinline__ float2 unpack2(unsigned long long v) {
    float2 f;
    asm("mov.b64 {%0, %1}, %2;" : "=f"(f.x), "=f"(f.y) : "l"(v));
    return f;
}
__device__ __forceinline__ void bar_group(int id) {
    asm volatile("bar.sync %0, %1;" :: "r"(id), "r"(TPB) : "memory");
}

// Load logical row r (swizzled chunks) into f[16].
__device__ __forceinline__ void load_row_sw(const __half* pb, int r,
                                            float f[CO]) {
    const uint2* base = (const uint2*)(pb + (size_t)r * PSTR);
    const int d = (r >> 2) & 3;
    #pragma unroll
    for (int q = 0; q < 4; ++q) {
        const uint2 u = base[q ^ d];
        const float2 f0 = __half22float2(*(const __half2*)&u.x);
        const float2 f1 = __half22float2(*(const __half2*)&u.y);
        f[q*4+0] = f0.x; f[q*4+1] = f0.y; f[q*4+2] = f1.x; f[q*4+3] = f1.y;
    }
}

// Split-exchange reduce of S[16] over 32 lanes: 16 shfl total.
__device__ __forceinline__ void reduce_s16(float S[CO], int lane,
                                           float* sred_warp) {
    const bool h16 = lane & 16;
    #pragma unroll
    for (int j = 0; j < 8; ++j) {
        const float snd = h16 ? S[j] : S[j + 8];
        const float kp  = h16 ? S[j + 8] : S[j];
        S[j] = kp + __shfl_xor_sync(0xffffffffu, snd, 16);
    }
    const bool h8 = lane & 8;
    #pragma unroll
    for (int j = 0; j < 4; ++j) {
        const float snd = h8 ? S[j] : S[j + 4];
        const float kp  = h8 ? S[j + 4] : S[j];
        S[j] = kp + __shfl_xor_sync(0xffffffffu, snd, 8);
    }
    const bool h4 = lane & 4;
    #pragma unroll
    for (int j = 0; j < 2; ++j) {
        const float snd = h4 ? S[j] : S[j + 2];
        const float kp  = h4 ? S[j + 2] : S[j];
        S[j] = kp + __shfl_xor_sync(0xffffffffu, snd, 4);
    }
    const bool h2 = lane & 2;
    {
        const float snd = h2 ? S[0] : S[1];
        const float kp  = h2 ? S[1] : S[0];
        S[0] = kp + __shfl_xor_sync(0xffffffffu, snd, 2);
    }
    S[0] += __shfl_xor_sync(0xffffffffu, S[0], 1);
    const int comp = ((lane >> 4) & 1) * 8 + ((lane >> 3) & 1) * 4 +
                     ((lane >> 2) & 1) * 2 + ((lane >> 1) & 1);
    if (!(lane & 1)) sred_warp[comp] = S[0];
}

// ---------- W repack: one thread per output float4 ----------
__global__ void __launch_bounds__(256)
repack_kernel(const float* __restrict__ W) {
    const int idx = blockIdx.x * blockDim.x + threadIdx.x;
    if (idx >= NCAPS * OCT * CI * 32) return;
    const int oq = idx & 3;
    const int rq = (idx >> 2) & 7;
    const int i  = (idx >> 5) & 7;
    const int rb = idx >> 8;               // n*OCT + g
    const float4* src = (const float4*)W + ((size_t)(rb * 8 + rq) * 8 + i) * 4 + oq;
    ((float4*)caps_Wq2)[idx] = *src;
}

__global__ void __launch_bounds__(NTHREADS, 1)
caps_kernel(const float* __restrict__ x,
            float* __restrict__ out) {
    extern __shared__ char smem[];
    __half* p   = (__half*)smem;
    float* sred = (float*)(smem + SRED_OFF);
    float* wred = (float*)(smem + WRED_OFF);
    float* vdot = (float*)(smem + VDOT_OFF);

    const int n  = blockIdx.y;
    const int b0 = blockIdx.x * BT;
    const int t  = threadIdx.x;
    const int wid  = t >> 5;
    const int lane = t & 31;

    // ======== Phase 1: priors GEMM (octet mapping) ========
    // lane = (rq 0..7, oq 0..3)
    {
        const int rq = lane >> 2;
        const int oq = lane & 3;
        #pragma unroll 1
        for (int j = 0; j < JIT; ++j) {
            const int g = wid + j * NWARP;
            const int r = g * 8 + rq;
            const int d = (r >> 2) & 3;
            // W: 8 contiguous-warp LDG.128 (512B each instr)
            const float4* wq =
                (const float4*)caps_Wq2 + ((size_t)(n * OCT + g) * 8) * 32
                + rq * 4 + oq;
            float4 wc[CI];
            #pragma unroll
            for (int i = 0; i < CI; ++i) wc[i] = wq[i * 32];

            // b-pair split keeps live registers ~70
            #pragma unroll
            for (int bp = 0; bp < 2; ++bp) {
                float xv[2][CI];
                #pragma unroll
                for (int bb = 0; bb < 2; ++bb) {
                    const int b = bp * 2 + bb;
                    const float4* xp =
                        (const float4*)(x + ((size_t)(b0 + b) * NR + r) * CI);
                    const float4 x0 = xp[0], x1 = xp[1];
                    xv[bb][0]=x0.x; xv[bb][1]=x0.y; xv[bb][2]=x0.z; xv[bb][3]=x0.w;
                    xv[bb][4]=x1.x; xv[bb][5]=x1.y; xv[bb][6]=x1.z; xv[bb][7]=x1.w;
                }
                unsigned long long acc[2][2];
                acc[0][0]=0ull; acc[0][1]=0ull; acc[1][0]=0ull; acc[1][1]=0ull;
                #pragma unroll
                for (int i = 0; i < CI; ++i) {
                    const unsigned long long wlo = packf2(wc[i].x, wc[i].y);
                    const unsigned long long whi = packf2(wc[i].z, wc[i].w);
                    #pragma unroll
                    for (int bb = 0; bb < 2; ++bb) {
                        const unsigned long long xx = pack2(xv[bb][i]);
                        fma2(acc[bb][0], xx, wlo);
                        fma2(acc[bb][1], xx, whi);
                    }
                }
                #pragma unroll
                for (int bb = 0; bb < 2; ++bb) {
                    const int b = bp * 2 + bb;
                    const float2 f0 = unpack2(acc[bb][0]);
                    const float2 f1 = unpack2(acc[bb][1]);
                    H4 h;
                    h.a = __floats2half2_rn(f0.x, f0.y);
                    h.b = __floats2half2_rn(f1.x, f1.y);
                    // swizzled chunk store (conflict-free STS.64)
                    *(H4*)(p + (size_t)(b * NR + r) * PSTR + ((oq ^ d) << 2)) = h;
                }
            }
        }
    }
    __syncthreads();

    // ======== Phase 2: routing, streamed rows, max-free softmax ========
    const int b    = t / TPB;      // 0..3
    const int tb   = t % TPB;      // 0..191
    const int wl   = tb >> 5;      // warp in group 0..5
    const int bid  = b + 1;
    const __half* pb = p + (size_t)b * NR * PSTR;
    float* sredb = sred + b * WPG * CO;
    float* wredb = wred + b * WPG;
    float* vdotb = vdot + b * CO;

    // ---- v0 = squash(mean_r p_r): one streamed pass ----
    {
        float S[CO];
        #pragma unroll
        for (int o = 0; o < CO; ++o) S[o] = 0.f;
        #pragma unroll
        for (int k = 0; k < KPT; ++k) {
            float f[CO];
            load_row_sw(pb, tb + k * TPB, f);
            #pragma unroll
            for (int o = 0; o < CO; ++o) S[o] += f[o];
        }
        reduce_s16(S, lane, sredb + wl * CO);
        bar_group(bid);
        if (tb < CO) {
            float s = 0.f;
            #pragma unroll
            for (int w = 0; w < WPG; ++w) s += sredb[w * CO + tb];
            const float v = s * (1.0f / NR);
            float sq = v * v;
            #pragma unroll
            for (int off = 8; off; off >>= 1)
                sq += __shfl_xor_sync(0xffffu, sq, off);
            const float coef = sq / ((1.f + sq) * sqrtf(sq));
            vdotb[tb] = v * coef;
        }
        bar_group(bid);
    }

    // ---- rounds 1 and 2: single fused streamed pass per round ----
    #pragma unroll
    for (int round = 0; round < 2; ++round) {
        float vd[CO];
        #pragma unroll
        for (int o = 0; o < CO; ++o) vd[o] = vdotb[o];

        float S[CO];
        #pragma unroll
        for (int o = 0; o < CO; ++o) S[o] = 0.f;
        float zloc = 0.f;

        #pragma unroll
        for (int k = 0; k < KPT; ++k) {
            float f[CO];
            load_row_sw(pb, tb + k * TPB, f);
            float a = 0.f;
            #pragma unroll
            for (int o = 0; o < CO; ++o) a += f[o] * vd[o];
            const float e = __expf(a);      // max-free: |a| <~ 20, safe
            zloc += e;
            #pragma unroll
            for (int o = 0; o < CO; ++o) S[o] += e * f[o];
        }
        #pragma unroll
        for (int off = 16; off; off >>= 1)
            zloc += __shfl_xor_sync(0xffffffffu, zloc, off);
        if (lane == 0) wredb[wl] = zloc;
        reduce_s16(S, lane, sredb + wl * CO);
        bar_group(bid);

        if (tb < CO) {
            float s = 0.f;
            #pragma unroll
            for (int w = 0; w < WPG; ++w) s += sredb[w * CO + tb];
            float Z = wredb[0];
            #pragma unroll
            for (int w = 1; w < WPG; ++w) Z += wredb[w];
            const float v = s / Z;
            float sq = v * v;
            #pragma unroll
            for (int off = 8; off; off >>= 1)
                sq += __shfl_xor_sync(0xffffu, sq, off);
            const float coef = sq / ((1.f + sq) * sqrtf(sq));
            const float res = v * coef;
            if (round == 0)
                vdotb[tb] += res;                       // w = v0 + v1
            else
                out[((size_t)n * NB + (b0 + b)) * CO + tb] = res;
        }
        bar_group(bid);
    }
}

extern "C" void kernel_launch(void* const* d_in, const int* in_sizes, int n_in,
                              void* d_out, int out_size) {
    (void)in_sizes; (void)n_in; (void)out_size;
    const float* x = (const float*)d_in[0];
    const float* W = (const float*)d_in[1];
    float* out = (float*)d_out;

    const int total = NCAPS * OCT * CI * 32;
    repack_kernel<<<(total + 255) / 256, 256>>>(W);

    cudaFuncSetAttribute(caps_kernel,
                         cudaFuncAttributeMaxDynamicSharedMemorySize, SMEM_TOTAL);
    dim3 grid(GROUPS, NCAPS);
    caps_kernel<<<grid, NTHREADS, SMEM_TOTAL>>>(x, out);
}